// round 4
// baseline (speedup 1.0000x reference)
#include <cuda_runtime.h>
#include <stdint.h>
#include <math.h>

// Problem dims
#define BQ 256
#define TQ 128
#define DETERQ 512
#define HIDQ 512
#define TOTQ 1024
#define OBSQ 768
#define ACTQ 7
#define FEATQ 3584   // 512 deter + 1024 stoch + 1024 prior + 1024 post

// ---------------- device scratch (no allocations allowed) ----------------
__device__ float g_post_obs[(size_t)BQ * TQ * HIDQ];   // o_t @ post_w1[512:1280]
__device__ float g_deter[2][BQ * DETERQ];              // ping-pong deter buffers
__device__ float g_h[BQ * 2 * HIDQ];                   // [elu prior hidden | elu post hidden]
__device__ int   g_idx[BQ * 32];
__device__ uint2 g_keys[TQ];

// ---------------- threefry2x32 (JAX-exact, 20 rounds) ----------------
__device__ __forceinline__ uint32_t rotl32(uint32_t x, int d) {
    return (x << d) | (x >> (32 - d));
}
__device__ __forceinline__ void tf_round4(uint32_t& x0, uint32_t& x1,
                                          int r0, int r1, int r2, int r3) {
    x0 += x1; x1 = rotl32(x1, r0); x1 ^= x0;
    x0 += x1; x1 = rotl32(x1, r1); x1 ^= x0;
    x0 += x1; x1 = rotl32(x1, r2); x1 ^= x0;
    x0 += x1; x1 = rotl32(x1, r3); x1 ^= x0;
}
__device__ __forceinline__ void threefry2x32(uint32_t k0, uint32_t k1,
                                             uint32_t c0, uint32_t c1,
                                             uint32_t& o0, uint32_t& o1) {
    uint32_t ks2 = k0 ^ k1 ^ 0x1BD11BDAu;
    uint32_t x0 = c0 + k0, x1 = c1 + k1;
    tf_round4(x0, x1, 13, 15, 26, 6);  x0 += k1;  x1 += ks2 + 1u;
    tf_round4(x0, x1, 17, 29, 16, 24); x0 += ks2; x1 += k0 + 2u;
    tf_round4(x0, x1, 13, 15, 26, 6);  x0 += k0;  x1 += k1 + 3u;
    tf_round4(x0, x1, 17, 29, 16, 24); x0 += k1;  x1 += ks2 + 4u;
    tf_round4(x0, x1, 13, 15, 26, 6);  x0 += ks2; x1 += k0 + 5u;
    o0 = x0; o1 = x1;
}

__device__ __forceinline__ float gumbel_of(uint2 key, uint32_t e) {
    uint32_t o0, o1;
    threefry2x32(key.x, key.y, 0u, e, o0, o1);
    uint32_t bits = o0 ^ o1;
    float f = __uint_as_float((bits >> 9) | 0x3f800000u) - 1.0f;
    float u = fmaxf(1.17549435e-38f, f);
    return -logf(-logf(u));
}

// ---------------- init: zero deter buf0, derive per-step keys ----------------
__global__ void init_kernel() {
    int i = blockIdx.x * 256 + threadIdx.x;
    if (i < BQ * DETERQ) g_deter[0][i] = 0.0f;
    if (blockIdx.x == 0 && threadIdx.x < TQ) {
        uint32_t t = threadIdx.x;
        uint32_t o0, o1;
        threefry2x32(0u, 42u, 0u, t, o0, o1);   // partitionable fold-in split
        g_keys[t] = make_uint2(o0, o1);
    }
}

// ---------------- big hoisted GEMM: 128x128 tile, 8x8 microtile, dbuf ----------------
// C[32768,512] = A[32768,768] @ B[768,512]
__global__ __launch_bounds__(256) void obs_gemm_kernel(const float* __restrict__ A,
                                                       const float* __restrict__ B,
                                                       float* __restrict__ C) {
    __shared__ __align__(16) float As[2][8][132];
    __shared__ __align__(16) float Bs[2][8][128];
    int bm = blockIdx.y * 128;
    int bn = blockIdx.x * 128;
    int tid = threadIdx.x;
    int tx = tid & 15, ty = tid >> 4;

    int arow = tid >> 1, ak = (tid & 1) * 4;
    int bk = tid >> 5, bn4 = (tid & 31) * 4;
    const float* aptr = A + (size_t)(bm + arow) * OBSQ + ak;
    const float* bptr = B + (size_t)bk * 512 + bn + bn4;

    float acc[8][8];
#pragma unroll
    for (int i = 0; i < 8; i++)
#pragma unroll
        for (int j = 0; j < 8; j++) acc[i][j] = 0.0f;

    float4 av = *(const float4*)aptr;
    float4 bv = *(const float4*)bptr;
    As[0][ak + 0][arow] = av.x; As[0][ak + 1][arow] = av.y;
    As[0][ak + 2][arow] = av.z; As[0][ak + 3][arow] = av.w;
    *(float4*)&Bs[0][bk][bn4] = bv;
    __syncthreads();

    const int NT = OBSQ / 8;   // 96
    for (int kt = 0; kt < NT; kt++) {
        int cur = kt & 1;
        if (kt + 1 < NT) {
            av = *(const float4*)(aptr + (kt + 1) * 8);
            bv = *(const float4*)(bptr + (size_t)(kt + 1) * 8 * 512);
        }
#pragma unroll
        for (int kk = 0; kk < 8; kk++) {
            float4 a0 = *(const float4*)&As[cur][kk][ty * 8];
            float4 a1 = *(const float4*)&As[cur][kk][ty * 8 + 4];
            float4 b0 = *(const float4*)&Bs[cur][kk][tx * 8];
            float4 b1 = *(const float4*)&Bs[cur][kk][tx * 8 + 4];
            float a[8] = {a0.x, a0.y, a0.z, a0.w, a1.x, a1.y, a1.z, a1.w};
            float b[8] = {b0.x, b0.y, b0.z, b0.w, b1.x, b1.y, b1.z, b1.w};
#pragma unroll
            for (int i = 0; i < 8; i++)
#pragma unroll
                for (int j = 0; j < 8; j++) acc[i][j] += a[i] * b[j];
        }
        if (kt + 1 < NT) {
            int nxt = cur ^ 1;
            As[nxt][ak + 0][arow] = av.x; As[nxt][ak + 1][arow] = av.y;
            As[nxt][ak + 2][arow] = av.z; As[nxt][ak + 3][arow] = av.w;
            *(float4*)&Bs[nxt][bk][bn4] = bv;
            __syncthreads();
        }
    }
#pragma unroll
    for (int i = 0; i < 8; i++) {
        size_t row = (size_t)(bm + ty * 8 + i);
        float4 c0 = make_float4(acc[i][0], acc[i][1], acc[i][2], acc[i][3]);
        float4 c1 = make_float4(acc[i][4], acc[i][5], acc[i][6], acc[i][7]);
        *(float4*)(C + row * 512 + bn + tx * 8) = c0;
        *(float4*)(C + row * 512 + bn + tx * 8 + 4) = c1;
    }
}

// ---------------- fused gh-GEMM + gather-gi + GRU ----------------
// Block: 32 rows (b) x 32 deter-cols (d), computes all 3 gates (N cols d, 512+d, 1024+d).
__global__ __launch_bounds__(128) void ghgru_kernel(
    const float* __restrict__ dprev, float* __restrict__ dnext,
    const float* __restrict__ w_hh, const float* __restrict__ b_hh,
    const float* __restrict__ w_ih, const float* __restrict__ b_ih,
    const float* __restrict__ actions, float* __restrict__ out, int t)
{
    __shared__ __align__(16) float As[2][16][36];
    __shared__ __align__(16) float Bs[2][16][96];
    __shared__ float s_wact[ACTQ][96];
    __shared__ float s_act[32][ACTQ];
    __shared__ int   s_idx[32][32];

    int d0 = blockIdx.x * 32;
    int bm = blockIdx.y * 32;
    int tid = threadIdx.x;
    int tx = tid & 15, ty = tid >> 4;

    // one-time smem: action weights / actions / gather indices
    for (int i = tid; i < ACTQ * 96; i += 128) {
        int r = i / 96, c = i % 96; int g = c >> 5, n = c & 31;
        s_wact[r][c] = w_ih[(size_t)(TOTQ + r) * (3 * DETERQ) + g * DETERQ + d0 + n];
    }
    for (int i = tid; i < 32 * ACTQ; i += 128) {
        int b = i / ACTQ, j = i % ACTQ;
        s_act[b][j] = actions[((size_t)(bm + b) * TQ + t) * ACTQ + j];
    }
    if (t > 0) {
        for (int i = tid; i < 1024; i += 128)
            s_idx[i >> 5][i & 31] = g_idx[(bm + (i >> 5)) * 32 + (i & 31)];
    }

    int arow = tid >> 2, ak = (tid & 3) << 2;
    int bk = tid >> 3, bn = (tid & 7) << 2;
    const float* aptr = dprev + (size_t)(bm + arow) * DETERQ + ak;
    const float* bptr = w_hh + (size_t)bk * (3 * DETERQ) + d0 + bn;

    float acc[3][4][2];
#pragma unroll
    for (int g = 0; g < 3; g++)
#pragma unroll
        for (int i = 0; i < 4; i++) { acc[g][i][0] = 0.0f; acc[g][i][1] = 0.0f; }

    float4 av = *(const float4*)aptr;
    float4 bv0 = *(const float4*)(bptr);
    float4 bv1 = *(const float4*)(bptr + DETERQ);
    float4 bv2 = *(const float4*)(bptr + 2 * DETERQ);
    As[0][ak + 0][arow] = av.x; As[0][ak + 1][arow] = av.y;
    As[0][ak + 2][arow] = av.z; As[0][ak + 3][arow] = av.w;
    *(float4*)&Bs[0][bk][bn]      = bv0;
    *(float4*)&Bs[0][bk][32 + bn] = bv1;
    *(float4*)&Bs[0][bk][64 + bn] = bv2;
    __syncthreads();

    const int NT = DETERQ / 16;  // 32
    for (int kt = 0; kt < NT; kt++) {
        int cur = kt & 1;
        if (kt + 1 < NT) {
            const float* ap = aptr + (kt + 1) * 16;
            const float* bp = bptr + (size_t)(kt + 1) * 16 * (3 * DETERQ);
            av  = *(const float4*)ap;
            bv0 = *(const float4*)(bp);
            bv1 = *(const float4*)(bp + DETERQ);
            bv2 = *(const float4*)(bp + 2 * DETERQ);
        }
#pragma unroll
        for (int kk = 0; kk < 16; kk++) {
            float4 a4 = *(const float4*)&As[cur][kk][ty * 4];
            float a[4] = {a4.x, a4.y, a4.z, a4.w};
#pragma unroll
            for (int g = 0; g < 3; g++) {
                float2 b2 = *(const float2*)&Bs[cur][kk][g * 32 + tx * 2];
#pragma unroll
                for (int i = 0; i < 4; i++) {
                    acc[g][i][0] += a[i] * b2.x;
                    acc[g][i][1] += a[i] * b2.y;
                }
            }
        }
        if (kt + 1 < NT) {
            int nxt = cur ^ 1;
            As[nxt][ak + 0][arow] = av.x; As[nxt][ak + 1][arow] = av.y;
            As[nxt][ak + 2][arow] = av.z; As[nxt][ak + 3][arow] = av.w;
            *(float4*)&Bs[nxt][bk][bn]      = bv0;
            *(float4*)&Bs[nxt][bk][32 + bn] = bv1;
            *(float4*)&Bs[nxt][bk][64 + bn] = bv2;
            __syncthreads();
        }
    }

    // epilogue: gi = b_ih + one-hot gather + action matvec; then GRU pointwise
#pragma unroll
    for (int i = 0; i < 4; i++) {
        int row = bm + ty * 4 + i;
        float gi[3][2];
#pragma unroll
        for (int g = 0; g < 3; g++) {
            gi[g][0] = b_ih[g * DETERQ + d0 + tx * 2 + 0];
            gi[g][1] = b_ih[g * DETERQ + d0 + tx * 2 + 1];
        }
        if (t > 0) {
#pragma unroll 4
            for (int s = 0; s < 32; s++) {
                const float* wr = w_ih + (size_t)(s * 32 + s_idx[ty * 4 + i][s]) * (3 * DETERQ)
                                  + d0 + tx * 2;
#pragma unroll
                for (int g = 0; g < 3; g++) {
                    gi[g][0] += wr[g * DETERQ + 0];
                    gi[g][1] += wr[g * DETERQ + 1];
                }
            }
        }
#pragma unroll
        for (int r = 0; r < ACTQ; r++) {
            float a = s_act[ty * 4 + i][r];
#pragma unroll
            for (int g = 0; g < 3; g++) {
                gi[g][0] += a * s_wact[r][g * 32 + tx * 2 + 0];
                gi[g][1] += a * s_wact[r][g * 32 + tx * 2 + 1];
            }
        }
#pragma unroll
        for (int j = 0; j < 2; j++) {
            int d = d0 + tx * 2 + j;
            float ghr = acc[0][i][j] + b_hh[d];
            float ghz = acc[1][i][j] + b_hh[DETERQ + d];
            float ghn = acc[2][i][j] + b_hh[2 * DETERQ + d];
            float rr = 1.0f / (1.0f + expf(-(gi[0][j] + ghr)));
            float zz = 1.0f / (1.0f + expf(-(gi[1][j] + ghz)));
            float nn = tanhf(gi[2][j] + rr * ghn);
            float dp = dprev[(size_t)row * DETERQ + d];
            float dn = (1.0f - zz) * nn + zz * dp;
            dnext[(size_t)row * DETERQ + d] = dn;
            out[((size_t)row * TQ + t) * FEATQ + d] = dn;
        }
    }
}

// ---------------- generic fp32 GEMM with split-N + epilogue (+optional sampler) ----------------
struct GemmP {
    const float* A; int lda; int acol2;
    const float* B1; const float* B2; int ldb;
    const float* bias1; const float* bias2;
    const float* extra2; int ld_extra;
    float* C; long long ldc;
    int M, N, K, nsplit;
    int act;       // 0 = none, 1 = ELU
    int sample;    // 1 = gumbel argmax over post-half 32-col groups
    int t;
    float* stoch;  // one-hot dest (row stride = ldc)
};

__global__ __launch_bounds__(128) void gemm_kernel(GemmP p) {
    __shared__ __align__(16) float As[16][36];
    __shared__ __align__(16) float Bs[16][64];
    int bn = blockIdx.x * 64;
    int bm = blockIdx.y * 32;
    bool second = (bn >= p.nsplit);
    const float* B    = second ? p.B2 : p.B1;
    const float* bias = second ? p.bias2 : p.bias1;
    const float* A    = p.A + (second ? p.acol2 : 0);
    int bcol = second ? (bn - p.nsplit) : bn;

    int tid = threadIdx.x;
    int tx = tid & 15, ty = tid >> 4;

    float acc[4][4];
#pragma unroll
    for (int i = 0; i < 4; i++)
#pragma unroll
        for (int j = 0; j < 4; j++) acc[i][j] = 0.0f;

    int arow = tid >> 2;
    int akq  = (tid & 3) << 2;
    int bk   = tid >> 4;
    int bnn  = (tid & 15) << 2;

    const float* aptr = A + (size_t)(bm + arow) * p.lda + akq;
    const float* bptr = B + (size_t)bk * p.ldb + bcol + bnn;

    float4 av  = *(const float4*)(aptr);
    float4 bv0 = *(const float4*)(bptr);
    float4 bv1 = *(const float4*)(bptr + 8 * (size_t)p.ldb);

    for (int k0 = 0; k0 < p.K; k0 += 16) {
        As[akq + 0][arow] = av.x;
        As[akq + 1][arow] = av.y;
        As[akq + 2][arow] = av.z;
        As[akq + 3][arow] = av.w;
        *(float4*)&Bs[bk][bnn]     = bv0;
        *(float4*)&Bs[bk + 8][bnn] = bv1;
        __syncthreads();

        if (k0 + 16 < p.K) {
            av  = *(const float4*)(aptr + k0 + 16);
            bv0 = *(const float4*)(bptr + (size_t)(k0 + 16) * p.ldb);
            bv1 = *(const float4*)(bptr + (size_t)(k0 + 24) * p.ldb);
        }
#pragma unroll
        for (int kk = 0; kk < 16; kk++) {
            float a0 = As[kk][ty * 4 + 0], a1 = As[kk][ty * 4 + 1];
            float a2 = As[kk][ty * 4 + 2], a3 = As[kk][ty * 4 + 3];
            float b0 = Bs[kk][tx * 4 + 0], b1 = Bs[kk][tx * 4 + 1];
            float b2 = Bs[kk][tx * 4 + 2], b3 = Bs[kk][tx * 4 + 3];
            acc[0][0] += a0 * b0; acc[0][1] += a0 * b1; acc[0][2] += a0 * b2; acc[0][3] += a0 * b3;
            acc[1][0] += a1 * b0; acc[1][1] += a1 * b1; acc[1][2] += a1 * b2; acc[1][3] += a1 * b3;
            acc[2][0] += a2 * b0; acc[2][1] += a2 * b1; acc[2][2] += a2 * b2; acc[2][3] += a2 * b3;
            acc[3][0] += a3 * b0; acc[3][1] += a3 * b1; acc[3][2] += a3 * b2; acc[3][3] += a3 * b3;
        }
        __syncthreads();
    }

    float lv[4][4];
#pragma unroll
    for (int i = 0; i < 4; i++) {
        int row = bm + ty * 4 + i;
#pragma unroll
        for (int j = 0; j < 4; j++) {
            int cl = bcol + tx * 4 + j;
            float v = acc[i][j];
            if (bias) v += bias[cl];
            if (second && p.extra2) v += p.extra2[(size_t)row * p.ld_extra + cl];
            if (p.act == 1) v = (v > 0.0f) ? v : expm1f(v);
            lv[i][j] = v;
            p.C[(size_t)row * (size_t)p.ldc + bn + tx * 4 + j] = v;
        }
    }

    // fused sampler over post-logit 32-col groups (exact R2 semantics)
    if (p.sample && second) {
        int lane = tid & 31;
        int pc0 = (bn - p.nsplit) + tx * 4;  // post col of j=0 (group-aligned per thread)
        int sg = pc0 >> 5;
        int cb = pc0 & 31;
        uint2 key = g_keys[p.t];
#pragma unroll
        for (int i = 0; i < 4; i++) {
            int row = bm + ty * 4 + i;
            float best = -__int_as_float(0x7f800000);  // -inf
            int bidx = 0;
            uint32_t ebase = (uint32_t)row * 1024u + (uint32_t)sg * 32u + (uint32_t)cb;
#pragma unroll
            for (int j = 0; j < 4; j++) {
                float val = lv[i][j] + gumbel_of(key, ebase + (uint32_t)j);
                if (val > best) { best = val; bidx = cb + j; }
            }
#pragma unroll
            for (int off = 4; off > 0; off >>= 1) {
                float ov = __shfl_down_sync(0xffffffffu, best, off, 8);
                int   oi = __shfl_down_sync(0xffffffffu, bidx, off, 8);
                if (ov > best || (ov == best && oi < bidx)) { best = ov; bidx = oi; }
            }
            int win = __shfl_sync(0xffffffffu, bidx, 0, 8);
#pragma unroll
            for (int j = 0; j < 4; j++)
                p.stoch[(size_t)row * (size_t)p.ldc + sg * 32 + cb + j] =
                    (cb + j == win) ? 1.0f : 0.0f;
            if ((lane & 7) == 0) g_idx[row * 32 + sg] = win;
        }
    }
}

// ---------------- host launcher ----------------
extern "C" void kernel_launch(void* const* d_in, const int* in_sizes, int n_in,
                              void* d_out, int out_size) {
    (void)in_sizes; (void)n_in; (void)out_size;
    const float* obs      = (const float*)d_in[0];
    const float* actions  = (const float*)d_in[1];
    const float* w_ih     = (const float*)d_in[2];
    const float* w_hh     = (const float*)d_in[3];
    const float* b_ih     = (const float*)d_in[4];
    const float* b_hh     = (const float*)d_in[5];
    const float* prior_w1 = (const float*)d_in[6];
    const float* prior_b1 = (const float*)d_in[7];
    const float* prior_w2 = (const float*)d_in[8];
    const float* prior_b2 = (const float*)d_in[9];
    const float* post_w1  = (const float*)d_in[10];
    const float* post_b1  = (const float*)d_in[11];
    const float* post_w2  = (const float*)d_in[12];
    const float* post_b2  = (const float*)d_in[13];
    float* out = (float*)d_out;

    void *p_po, *p_h, *p_deter;
    cudaGetSymbolAddress(&p_po, g_post_obs);
    cudaGetSymbolAddress(&p_h, g_h);
    cudaGetSymbolAddress(&p_deter, g_deter);
    float* post_obs = (float*)p_po;
    float* h     = (float*)p_h;
    float* bufA  = (float*)p_deter;
    float* bufB  = bufA + BQ * DETERQ;

    init_kernel<<<512, 256>>>();

    // Hoisted: post_obs = obs @ post_w1[512:1280]
    obs_gemm_kernel<<<dim3(512 / 128, (BQ * TQ) / 128), 256>>>(
        obs, post_w1 + (size_t)DETERQ * HIDQ, post_obs);

    for (int t = 0; t < TQ; t++) {
        float* dprev = (t & 1) ? bufB : bufA;
        float* dnext = (t & 1) ? bufA : bufB;

        // fused gh GEMM + gather gi + GRU -> dnext, out[:,t,0:512]
        ghgru_kernel<<<dim3(DETERQ / 32, BQ / 32), 128>>>(
            dprev, dnext, w_hh, b_hh, w_ih, b_ih, actions, out, t);

        // h = [ elu(deter@prior_w1 + b1) | elu(deter@post_w1[:512] + post_obs + b1) ]
        {
            GemmP p;
            p.A = dnext; p.lda = DETERQ; p.acol2 = 0;
            p.B1 = prior_w1; p.B2 = post_w1; p.ldb = HIDQ;
            p.bias1 = prior_b1; p.bias2 = post_b1;
            p.extra2 = post_obs + (size_t)t * HIDQ; p.ld_extra = TQ * HIDQ;
            p.C = h; p.ldc = 2 * HIDQ;
            p.M = BQ; p.N = 2 * HIDQ; p.K = DETERQ; p.nsplit = HIDQ; p.act = 1;
            p.sample = 0; p.t = t; p.stoch = nullptr;
            gemm_kernel<<<dim3((2 * HIDQ) / 64, BQ / 32), 128>>>(p);
        }
        // [prior_logits | post_logits] -> out[:,t,1536:3584], + fused sampler -> stoch, g_idx
        {
            GemmP p;
            p.A = h; p.lda = 2 * HIDQ; p.acol2 = HIDQ;
            p.B1 = prior_w2; p.B2 = post_w2; p.ldb = TOTQ;
            p.bias1 = prior_b2; p.bias2 = post_b2;
            p.extra2 = nullptr; p.ld_extra = 0;
            p.C = out + (size_t)t * FEATQ + 1536; p.ldc = (long long)TQ * FEATQ;
            p.M = BQ; p.N = 2 * TOTQ; p.K = HIDQ; p.nsplit = TOTQ; p.act = 0;
            p.sample = 1; p.t = t; p.stoch = out + (size_t)t * FEATQ + 512;
            gemm_kernel<<<dim3((2 * TOTQ) / 64, BQ / 32), 128>>>(p);
        }
    }
}